// round 3
// baseline (speedup 1.0000x reference)
#include <cuda_runtime.h>
#include <cstdint>

// ---------------- problem constants ----------------
constexpr int KS = 3;
constexpr int B  = 4, C = 64, H = 256, W = 512;
constexpr int S  = H * W;                 // 131072 spatial
constexpr int IW = KS * W;                // 1536 idx row width
constexpr int NIDX = KS * H * KS * W;     // 1179648
constexpr int NW   = C * C * KS * KS;     // 36864

// ---------------- main-kernel tiling ----------------
constexpr int PX      = 128;              // pixels per CTA tile (along ow)
constexpr int NTILES  = (B * H * W) / PX; // 4096
constexpr int NTHREADS = 256;             // 16 co-threads x 16 px-groups
constexpr int SMEM_W_FLOATS = 9 * 64 * 64;       // 36864
constexpr int XBUF_FLOATS   = PX * 64;           // 8192
constexpr int SMEM_BYTES = (SMEM_W_FLOATS + 2 * XBUF_FLOATS) * 4; // 212992

// ---------------- scratch (device globals: no allocs allowed) ----------------
__device__ float g_xT[(size_t)B * S * C];   // 128 MB: x transposed to [b][s][c]
__device__ int   g_idx[NIDX];               // idx as int32 (masked to [0,S))
__device__ float g_wr[NW];                  // weight as [t][ci][co]
__device__ int   g_ctr;                     // tile work counter

// ---------------- ptx helpers ----------------
__device__ __forceinline__ void fma2(unsigned long long& acc,
                                     unsigned long long w,
                                     unsigned long long x) {
    asm("fma.rn.f32x2 %0, %1, %2, %0;" : "+l"(acc) : "l"(w), "l"(x));
}
__device__ __forceinline__ unsigned long long bcast2(float f) {
    unsigned long long r;
    asm("mov.b64 %0, {%1, %1};" : "=l"(r) : "r"(__float_as_uint(f)));
    return r;
}
__device__ __forceinline__ void cp_async16(unsigned dst, const float* src) {
    asm volatile("cp.async.cg.shared.global [%0], [%1], 16;" :: "r"(dst), "l"(src));
}
__device__ __forceinline__ void cp_commit() {
    asm volatile("cp.async.commit_group;");
}

union F2U { unsigned long long u; float f[2]; };

// ---------------- kernel 1: transpose x[b][c][s] -> g_xT[b][s][c] ----------------
__global__ void k_transpose(const float* __restrict__ x) {
    __shared__ float tile[32][33];
    int b  = blockIdx.z;
    int c0 = blockIdx.y * 32;
    int s0 = blockIdx.x * 32;
    const float* xp = x + ((size_t)(b * C + c0)) * S + s0;
#pragma unroll
    for (int i = 0; i < 32; i += 8)
        tile[threadIdx.y + i][threadIdx.x] =
            xp[(size_t)(threadIdx.y + i) * S + threadIdx.x];
    __syncthreads();
    float* op = g_xT + ((size_t)b * S + s0) * C + c0;
#pragma unroll
    for (int i = 0; i < 32; i += 8)
        op[(size_t)(threadIdx.y + i) * C + threadIdx.x] =
            tile[threadIdx.x][threadIdx.y + i];
}

// ---------------- kernel 2: idx (int32 OR int64, auto-detected) -> int32 ----------------
// JAX with default x64-disabled config silently makes "int64" randint int32.
// Detect on device: read first 64 values as int64; if ALL are in [0, S) the
// buffer is真 int64 (for int32 data the odd words are random indices, so a
// 64-bit read is >= 2^32 unless the high word is 0 — all-64-pass prob ~0).
__global__ void k_idx(const void* __restrict__ idxraw) {
    const long long* p64 = (const long long*)idxraw;
    const int*       p32 = (const int*)idxraw;
    bool is64 = true;
#pragma unroll
    for (int j = 0; j < 64; j++) {
        long long v = p64[j];                 // 512 bytes, safe for either dtype
        if (v < 0 || v >= (long long)S) { is64 = false; break; }
    }
    int i = blockIdx.x * blockDim.x + threadIdx.x;
    if (i < NIDX) {
        int v = is64 ? (int)p64[i] : p32[i];
        g_idx[i] = v & (S - 1);               // S = 2^17: identity on valid data
    }
}

// ---------------- kernel 3: weight [co][ci][kh][kw] -> [t][ci][co]; reset counter ----------------
__global__ void k_prep(const float* __restrict__ w) {
    int i = blockIdx.x * blockDim.x + threadIdx.x;
    if (i == 0) g_ctr = 0;
    if (i < NW) {
        int co  = i / (C * KS * KS);
        int rem = i - co * (C * KS * KS);
        int ci  = rem / (KS * KS);
        int t   = rem - ci * (KS * KS);
        g_wr[t * (C * C) + ci * C + co] = w[i];
    }
}

// ---------------- main kernel helpers ----------------
__device__ __forceinline__ void decode_tile(int tau, int& b, int& oh, int& ow0) {
    b   = tau >> 10;            // 1024 tiles per batch (256 oh * 4)
    int r = tau & 1023;
    oh  = r >> 2;
    ow0 = (r & 3) * PX;
}

// gather one tap's 128 gathered rows (each 64 f32 = 256B) into smem via cp.async
__device__ __forceinline__ void gather_tap(int b, int oh, int ow0, int t, unsigned dst) {
    int kh = t / 3;
    int kw = t - 3 * kh;
    const int* ip = g_idx + (3 * oh + kh) * IW + 3 * ow0 + kw;
    const float* xb = g_xT + (size_t)b * ((size_t)S * C);
    int tid = threadIdx.x;
#pragma unroll
    for (int r = 0; r < (PX * 16) / NTHREADS; r++) {   // 8 iterations
        int e  = tid + r * NTHREADS;
        int p  = e >> 4;
        int c4 = e & 15;
        int sidx = ip[3 * p];
        const float* src = xb + ((size_t)sidx << 6) + (c4 << 2);
        cp_async16(dst + (unsigned)(e * 16), src);
    }
    cp_commit();
}

// per-tap compute: 4 co (pointer pre-offset) x 8 px per thread
__device__ __forceinline__ void compute_tap(const float* __restrict__ wp,   // sW + t*4096 + co0
                                            const float* __restrict__ xp,   // buf + px0*64
                                            unsigned long long accA[8],
                                            unsigned long long accB[8]) {
#pragma unroll 4
    for (int ci = 0; ci < 64; ci += 4) {
        unsigned long long wlo[4], whi[4];
#pragma unroll
        for (int j = 0; j < 4; j++) {
            ulonglong2 wv = *(const ulonglong2*)(wp + (ci + j) * 64);
            wlo[j] = wv.x;   // (co0, co0+1)
            whi[j] = wv.y;   // (co0+2, co0+3)
        }
#pragma unroll
        for (int p = 0; p < 8; p++) {
            float4 xv = *(const float4*)(xp + p * 64 + ci);
            unsigned long long x2;
            x2 = bcast2(xv.x); fma2(accA[p], wlo[0], x2); fma2(accB[p], whi[0], x2);
            x2 = bcast2(xv.y); fma2(accA[p], wlo[1], x2); fma2(accB[p], whi[1], x2);
            x2 = bcast2(xv.z); fma2(accA[p], wlo[2], x2); fma2(accB[p], whi[2], x2);
            x2 = bcast2(xv.w); fma2(accA[p], wlo[3], x2); fma2(accB[p], whi[3], x2);
        }
    }
}

// ---------------- main kernel: persistent, atomic-tile-stealing ----------------
__global__ void __launch_bounds__(NTHREADS, 1)
k_main(const float* __restrict__ bias, float* __restrict__ out) {
    extern __shared__ float smem[];
    float* sW  = smem;
    float* sX0 = smem + SMEM_W_FLOATS;
    float* sX1 = sX0 + XBUF_FLOATS;
    __shared__ int s_next;

    const int tid  = threadIdx.x;
    const int co_t = tid & 15;
    const int pxg  = tid >> 4;
    const int co0  = co_t * 4;
    const int px0  = pxg * 8;

    // stage all weights once (persistent CTA)
    {
        const float4* src4 = (const float4*)g_wr;
        float4* dst4 = (float4*)sW;
#pragma unroll
        for (int i = tid; i < SMEM_W_FLOATS / 4; i += NTHREADS) dst4[i] = src4[i];
    }

    const float4 bv = *(const float4*)(bias + co0);
    F2U tb0; tb0.f[0] = bv.x; tb0.f[1] = bv.y;
    F2U tb1; tb1.f[0] = bv.z; tb1.f[1] = bv.w;
    const unsigned long long bvA = tb0.u, bvB = tb1.u;

    const unsigned sx0a = (unsigned)__cvta_generic_to_shared(sX0);
    const unsigned sx1a = (unsigned)__cvta_generic_to_shared(sX1);

    if (tid == 0) s_next = atomicAdd(&g_ctr, 1);
    __syncthreads();   // also covers sW staging
    int tau = s_next;
    int pb = 0;

    if (tau < NTILES) {
        int b, oh, ow0; decode_tile(tau, b, oh, ow0);
        gather_tap(b, oh, ow0, 0, sx0a);
    }

    while (tau < NTILES) {
        if (tid == 0) s_next = atomicAdd(&g_ctr, 1);
        int b, oh, ow0; decode_tile(tau, b, oh, ow0);

        unsigned long long accA[8], accB[8];
#pragma unroll
        for (int p = 0; p < 8; p++) { accA[p] = bvA; accB[p] = bvB; }

        __syncthreads();          // publish s_next
        int ntau = s_next;
        int nb = 0, noh = 0, now0 = 0;
        if (ntau < NTILES) decode_tile(ntau, nb, noh, now0);

        for (int t = 0; t < 9; t++) {
            bool pf = true;
            unsigned nxt = (pb ^ 1) ? sx1a : sx0a;
            if (t < 8)                gather_tap(b, oh, ow0, t + 1, nxt);
            else if (ntau < NTILES)   gather_tap(nb, noh, now0, 0, nxt);
            else                      pf = false;
            if (pf) asm volatile("cp.async.wait_group 1;");
            else    asm volatile("cp.async.wait_group 0;");
            __syncthreads();
            const float* buf = pb ? sX1 : sX0;
            compute_tap(sW + t * (C * C) + co0, buf + px0 * 64, accA, accB);
            __syncthreads();       // before next gather overwrites this buffer
            pb ^= 1;
        }

        // store: repack per-co rows of 8 consecutive ow into float4s
        {
            F2U a[8], c[8];
#pragma unroll
            for (int p = 0; p < 8; p++) { a[p].u = accA[p]; c[p].u = accB[p]; }
            float* base = out + ((size_t)(b * C + co0)) * S + (size_t)oh * W + ow0 + px0;
#pragma unroll
            for (int h = 0; h < 2; h++) {
                float* bp = base + (size_t)h * S;            // co0 / co0+1
                *(float4*)(bp)     = make_float4(a[0].f[h], a[1].f[h], a[2].f[h], a[3].f[h]);
                *(float4*)(bp + 4) = make_float4(a[4].f[h], a[5].f[h], a[6].f[h], a[7].f[h]);
                float* cp2 = base + (size_t)(2 + h) * S;     // co0+2 / co0+3
                *(float4*)(cp2)     = make_float4(c[0].f[h], c[1].f[h], c[2].f[h], c[3].f[h]);
                *(float4*)(cp2 + 4) = make_float4(c[4].f[h], c[5].f[h], c[6].f[h], c[7].f[h]);
            }
        }
        tau = ntau;
    }
}

// ---------------- launch ----------------
extern "C" void kernel_launch(void* const* d_in, const int* in_sizes, int n_in,
                              void* d_out, int out_size) {
    (void)in_sizes; (void)n_in; (void)out_size;
    const float* x    = (const float*)d_in[0];
    const void*  idx  = d_in[1];             // int32 or int64, detected on device
    const float* w    = (const float*)d_in[2];
    const float* bias = (const float*)d_in[3];
    float* out = (float*)d_out;

    k_transpose<<<dim3(S / 32, C / 32, B), dim3(32, 8)>>>(x);
    k_idx<<<(NIDX + 1023) / 1024, 1024>>>(idx);
    k_prep<<<(NW + 255) / 256, 256>>>(w);

    cudaFuncSetAttribute(k_main, cudaFuncAttributeMaxDynamicSharedMemorySize, SMEM_BYTES);
    k_main<<<160, NTHREADS, SMEM_BYTES>>>(bias, out);
}

// round 13
// speedup vs baseline: 2.2587x; 2.2587x over previous
#include <cuda_runtime.h>
#include <cstdint>

// ---------------- problem constants ----------------
constexpr int KS = 3;
constexpr int B  = 4, C = 64, H = 256, W = 512;
constexpr int S  = H * W;                 // 131072
constexpr int IW = KS * W;                // 1536
constexpr int NIDX = KS * H * KS * W;     // 1179648
constexpr int NW   = C * C * KS * KS;     // 36864

constexpr int PX      = 128;
constexpr int NTILES  = (B * H * W) / PX; // 4096
constexpr int NTHREADS = 256;             // 8 warps

// smem layout (words)
constexpr int WF_WORDS   = 9 * 32 * 132;      // weight frags: 152064 B
constexpr int XSTRIDE    = 68;                // padded px row (conflict-free)
constexpr int XBUF_WORDS = PX * XSTRIDE;      // 34816 B per buffer
constexpr int SM_X0 = WF_WORDS;
constexpr int SM_X1 = WF_WORDS + XBUF_WORDS;
constexpr int SMEM_BYTES = (WF_WORDS + 2 * XBUF_WORDS) * 4;   // 221696

// ---------------- device scratch ----------------
__device__ float    g_xT[(size_t)B * S * C];  // x transposed [b][s][c]
__device__ int      g_idx[NIDX];
__device__ unsigned g_wf[WF_WORDS];           // tf32 weights in mma-fragment order
__device__ int      g_ctr;

extern __shared__ char dynsmem[];

// ---------------- ptx helpers ----------------
__device__ __forceinline__ unsigned smem_u32(const void* p) {
    unsigned a;
    asm("{ .reg .u64 t; cvta.to.shared.u64 t, %1; cvt.u32.u64 %0, t; }" : "=r"(a) : "l"(p));
    return a;
}
__device__ __forceinline__ void cp_async16(unsigned dst, const float* src) {
    asm volatile("cp.async.cg.shared.global [%0], [%1], 16;" :: "r"(dst), "l"(src));
}
__device__ __forceinline__ unsigned to_tf32(float f) {
    unsigned u;
    asm("cvt.rna.tf32.f32 %0, %1;" : "=r"(u) : "f"(f));
    return u;
}
__device__ __forceinline__ void mma_tf32(float c[4], const unsigned a[4],
                                         unsigned b0, unsigned b1) {
    asm volatile(
        "mma.sync.aligned.m16n8k8.row.col.f32.tf32.tf32.f32 "
        "{%0,%1,%2,%3}, {%4,%5,%6,%7}, {%8,%9}, {%0,%1,%2,%3};"
        : "+f"(c[0]), "+f"(c[1]), "+f"(c[2]), "+f"(c[3])
        : "r"(a[0]), "r"(a[1]), "r"(a[2]), "r"(a[3]), "r"(b0), "r"(b1));
}

// ---------------- kernel: transpose x[b][c][s] -> g_xT[b][s][c] ----------------
__global__ void k_transpose(const float* __restrict__ x) {
    __shared__ float tile[32][33];
    int b  = blockIdx.z;
    int c0 = blockIdx.y * 32;
    int s0 = blockIdx.x * 32;
    const float* xp = x + ((size_t)(b * C + c0)) * S + s0;
#pragma unroll
    for (int i = 0; i < 32; i += 8)
        tile[threadIdx.y + i][threadIdx.x] = xp[(size_t)(threadIdx.y + i) * S + threadIdx.x];
    __syncthreads();
    float* op = g_xT + ((size_t)b * S + s0) * C + c0;
#pragma unroll
    for (int i = 0; i < 32; i += 8)
        op[(size_t)(threadIdx.y + i) * C + threadIdx.x] = tile[threadIdx.x][threadIdx.y + i];
}

// ---------------- kernel: idx (int32 OR int64, auto-detected) ----------------
__global__ void k_idx(const void* __restrict__ idxraw) {
    const long long* p64 = (const long long*)idxraw;
    const int*       p32 = (const int*)idxraw;
    bool is64 = true;
#pragma unroll
    for (int j = 0; j < 64; j++) {
        long long v = p64[j];
        if (v < 0 || v >= (long long)S) { is64 = false; break; }
    }
    int i = blockIdx.x * blockDim.x + threadIdx.x;
    if (i < NIDX) {
        int v = is64 ? (int)p64[i] : p32[i];
        g_idx[i] = v & (S - 1);
    }
}

// ---------------- kernel: weights -> tf32 mma fragments; reset counter ----------
// mma.m16n8k8 A fragment (row-major M x K): for (co, ci) within (m-block, k-block):
//   lane = (row16 & 7)*4 + (ci & 3);  reg = ((row16 >> 3) & 1) + 2*((ci & 7) >> 2)
// stored per (tap, lane) contiguous so one ld.shared.v4 fetches a0..a3.
__global__ void k_prep(const float* __restrict__ w) {
    int i = blockIdx.x * blockDim.x + threadIdx.x;
    if (i == 0) g_ctr = 0;
    if (i < NW) {
        int co  = i / (C * KS * KS);
        int rem = i - co * (C * KS * KS);
        int ci  = rem / (KS * KS);
        int t   = rem - ci * (KS * KS);
        int m      = co >> 4;
        int row16  = co & 15;
        int half   = (row16 >> 3) & 1;
        int lanehi = row16 & 7;
        int kb     = ci >> 3;
        int cil    = ci & 7;
        int chalf  = cil >> 2;
        int lane   = lanehi * 4 + (cil & 3);
        int reg    = half + 2 * chalf;
        int word   = (t * 32 + lane) * 132 + (m * 8 + kb) * 4 + reg;
        g_wf[word] = to_tf32(w[i]);
    }
}

// ---------------- main kernel helpers ----------------
__device__ __forceinline__ void decode_tile(int tau, int& b, int& oh, int& ow0) {
    b = tau >> 10; int r = tau & 1023; oh = r >> 2; ow0 = (r & 3) * PX;
}

// gather one tap: 128 gathered rows (64 f32 each) into padded smem rows (272B)
__device__ __forceinline__ void gather_tap(int b, int oh, int ow0, int t, unsigned dstb) {
    int kh = t / 3, kw = t - 3 * kh;
    const int* ip = g_idx + (3 * oh + kh) * IW + 3 * ow0 + kw;
    const float* xb = g_xT + (size_t)b * ((size_t)S * C);
    int tid = threadIdx.x;
#pragma unroll
    for (int r = 0; r < (PX * 16) / NTHREADS; r++) {   // 8 iters
        int e  = tid + r * NTHREADS;
        int p  = e >> 4;
        int c4 = e & 15;
        int sidx = ip[3 * p];
        cp_async16(dstb + (unsigned)(p * 272 + c4 * 16),
                   xb + ((size_t)sidx << 6) + (c4 << 2));
    }
    asm volatile("cp.async.commit_group;");
}

// ---------------- main kernel: persistent, tf32 mma ----------------
__global__ void __launch_bounds__(NTHREADS, 1)
k_mma(const float* __restrict__ bias, float* __restrict__ out) {
    unsigned* sm = (unsigned*)dynsmem;
    __shared__ int s_next;

    const int tid  = threadIdx.x;
    const int wid  = tid >> 5;
    const int lane = tid & 31;
    const int lq   = lane >> 2;     // lane/4
    const int lr   = lane & 3;      // lane%4

    // stage weight fragments (152 KB) once
    {
        const uint4* src = (const uint4*)g_wf;
        uint4* dst = (uint4*)sm;
        for (int i = tid; i < WF_WORDS / 4; i += NTHREADS) dst[i] = src[i];
    }

    // bias per c-register row: co = m*16 + lq + 8*h
    float bco[4][2];
#pragma unroll
    for (int m = 0; m < 4; m++) {
        bco[m][0] = bias[m * 16 + lq];
        bco[m][1] = bias[m * 16 + lq + 8];
    }

    const unsigned sbase = smem_u32(sm);
    const unsigned sx0b  = sbase + SM_X0 * 4;
    const unsigned sx1b  = sbase + SM_X1 * 4;

    if (tid == 0) s_next = atomicAdd(&g_ctr, 1);
    __syncthreads();   // also covers weight staging
    int tau = s_next;
    int pb = 0;

    if (tau < NTILES) {
        int b, oh, ow0; decode_tile(tau, b, oh, ow0);
        gather_tap(b, oh, ow0, 0, sx0b);
    }

    while (tau < NTILES) {
        if (tid == 0) s_next = atomicAdd(&g_ctr, 1);
        int b, oh, ow0; decode_tile(tau, b, oh, ow0);

        float acc[4][2][4];
#pragma unroll
        for (int m = 0; m < 4; m++)
#pragma unroll
            for (int nb = 0; nb < 2; nb++)
#pragma unroll
                for (int c = 0; c < 4; c++) acc[m][nb][c] = 0.0f;

        __syncthreads();          // publish s_next
        int ntau = s_next;
        int nb_ = 0, noh = 0, now0 = 0;
        if (ntau < NTILES) decode_tile(ntau, nb_, noh, now0);

        for (int t = 0; t < 9; t++) {
            bool pf = true;
            unsigned nxt = (pb ^ 1) ? sx1b : sx0b;
            if (t < 8)              gather_tap(b, oh, ow0, t + 1, nxt);
            else if (ntau < NTILES) gather_tap(nb_, noh, now0, 0, nxt);
            else                    pf = false;
            if (pf) asm volatile("cp.async.wait_group 1;");
            else    asm volatile("cp.async.wait_group 0;");
            __syncthreads();

            // compute tap t from buffer pb
            const unsigned* xw = sm + (pb ? SM_X1 : SM_X0);
            const unsigned* wf = sm + (t * 32 + lane) * 132;
            const int n0 = wid * 16;        // this warp's px slice
#pragma unroll
            for (int kb = 0; kb < 8; kb++) {
                uint4 A[4];
#pragma unroll
                for (int m = 0; m < 4; m++)
                    A[m] = *(const uint4*)(wf + (m * 8 + kb) * 4);
                unsigned bfr[2][2];
#pragma unroll
                for (int nb = 0; nb < 2; nb++) {
                    const unsigned* xp = xw + (n0 + nb * 8 + lq) * XSTRIDE + kb * 8 + lr;
                    bfr[nb][0] = to_tf32(__uint_as_float(xp[0]));
                    bfr[nb][1] = to_tf32(__uint_as_float(xp[4]));
                }
#pragma unroll
                for (int m = 0; m < 4; m++)
#pragma unroll
                    for (int nb = 0; nb < 2; nb++)
                        mma_tf32(acc[m][nb], (const unsigned*)&A[m],
                                 bfr[nb][0], bfr[nb][1]);
            }
            __syncthreads();       // before next gather overwrites this buffer
            pb ^= 1;
        }

        // epilogue: c0/c1 -> (co, px), c2/c3 -> (co+8, px); px = 2*lr(+1)
        {
            float* obase = out + (size_t)b * C * S + (size_t)oh * W + ow0 + wid * 16;
#pragma unroll
            for (int m = 0; m < 4; m++) {
                int co0 = m * 16 + lq;
#pragma unroll
                for (int nb = 0; nb < 2; nb++) {
                    int px = nb * 8 + 2 * lr;
                    float2 v0 = make_float2(acc[m][nb][0] + bco[m][0],
                                            acc[m][nb][1] + bco[m][0]);
                    *(float2*)(obase + (size_t)co0 * S + px) = v0;
                    float2 v1 = make_float2(acc[m][nb][2] + bco[m][1],
                                            acc[m][nb][3] + bco[m][1]);
                    *(float2*)(obase + (size_t)(co0 + 8) * S + px) = v1;
                }
            }
        }
        tau = ntau;
    }
}

// ---------------- host launch ----------------
extern "C" void kernel_launch(void* const* d_in, const int* in_sizes, int n_in,
                              void* d_out, int out_size) {
    (void)in_sizes; (void)n_in; (void)out_size;
    const float* x    = (const float*)d_in[0];
    const void*  idx  = d_in[1];
    const float* w    = (const float*)d_in[2];
    const float* bias = (const float*)d_in[3];
    float* out = (float*)d_out;

    k_transpose<<<dim3(S / 32, C / 32, B), dim3(32, 8)>>>(x);
    k_idx<<<(NIDX + 1023) / 1024, 1024>>>(idx);
    k_prep<<<(NW + 255) / 256, 256>>>(w);

    cudaFuncSetAttribute(k_mma, cudaFuncAttributeMaxDynamicSharedMemorySize, SMEM_BYTES);
    k_mma<<<148, NTHREADS, SMEM_BYTES>>>(bias, out);
}

// round 14
// speedup vs baseline: 3.6370x; 1.6102x over previous
#include <cuda_runtime.h>
#include <cuda_fp16.h>
#include <cstdint>

// ---------------- problem constants ----------------
constexpr int KS = 3;
constexpr int B  = 4, C = 64, H = 256, W = 512;
constexpr int S  = H * W;                 // 131072
constexpr int IW = KS * W;                // 1536
constexpr int NIDX = KS * H * KS * W;     // 1179648
constexpr int NW   = C * C * KS * KS;     // 36864

constexpr int PX      = 256;              // pixels per tile
constexpr int NTILES  = (B * H * W) / PX; // 2048
constexpr int NTHREADS = 512;             // 16 warps

// smem layout (32-bit words)
constexpr int WLANE_STRIDE = 68;              // 64 frag words + 4 pad (bank-clean LDS.128)
constexpr int WF_WORDS   = 9 * 32 * WLANE_STRIDE;   // 19584 words = 78336 B
constexpr int XSTRIDE    = 36;                // 32 data words (64 half) + 4 pad
constexpr int XBUF_WORDS = PX * XSTRIDE;      // 9216 words = 36864 B per buffer
constexpr int SM_X0 = WF_WORDS;
constexpr int SM_X1 = WF_WORDS + XBUF_WORDS;
constexpr int SMEM_BYTES = (WF_WORDS + 2 * XBUF_WORDS) * 4;   // 152064

// ---------------- device scratch ----------------
__device__ __half   g_xh[(size_t)B * S * C];  // x transposed [b][s][c], fp16 (64 MB)
__device__ int      g_idx[NIDX];
__device__ unsigned g_wf[WF_WORDS];           // fp16 weights in m16n8k16 A-fragment order
__device__ int      g_ctr;

extern __shared__ char dynsmem[];

// ---------------- ptx helpers ----------------
__device__ __forceinline__ unsigned smem_u32(const void* p) {
    unsigned a;
    asm("{ .reg .u64 t; cvta.to.shared.u64 t, %1; cvt.u32.u64 %0, t; }" : "=r"(a) : "l"(p));
    return a;
}
__device__ __forceinline__ void cp_async16(unsigned dst, const void* src) {
    asm volatile("cp.async.cg.shared.global [%0], [%1], 16;" :: "r"(dst), "l"(src));
}
// mma.m16n8k16 f16 x f16 -> f32
__device__ __forceinline__ void mma_f16(float c[4], const unsigned a[4],
                                        unsigned b0, unsigned b1) {
    asm volatile(
        "mma.sync.aligned.m16n8k16.row.col.f32.f16.f16.f32 "
        "{%0,%1,%2,%3}, {%4,%5,%6,%7}, {%8,%9}, {%0,%1,%2,%3};"
        : "+f"(c[0]), "+f"(c[1]), "+f"(c[2]), "+f"(c[3])
        : "r"(a[0]), "r"(a[1]), "r"(a[2]), "r"(a[3]), "r"(b0), "r"(b1));
}

// ---------------- kernel: transpose x[b][c][s] -> g_xh[b][s][c] (fp16) ----------
__global__ void k_transpose(const float* __restrict__ x) {
    __shared__ float tile[32][33];
    int b  = blockIdx.z;
    int c0 = blockIdx.y * 32;
    int s0 = blockIdx.x * 32;
    const float* xp = x + ((size_t)(b * C + c0)) * S + s0;
#pragma unroll
    for (int i = 0; i < 32; i += 8)
        tile[threadIdx.y + i][threadIdx.x] = xp[(size_t)(threadIdx.y + i) * S + threadIdx.x];
    __syncthreads();
    __half* op = g_xh + ((size_t)b * S + s0) * C + c0;
    int t = threadIdx.x;
    if (t < 16) {
#pragma unroll
        for (int i = 0; i < 32; i += 8) {
            int row = threadIdx.y + i;
            half2 v = __floats2half2_rn(tile[2 * t][row], tile[2 * t + 1][row]);
            ((half2*)(op + (size_t)row * C))[t] = v;
        }
    }
}

// ---------------- kernel: idx (int32 OR int64, auto-detected) ----------------
__global__ void k_idx(const void* __restrict__ idxraw) {
    const long long* p64 = (const long long*)idxraw;
    const int*       p32 = (const int*)idxraw;
    bool is64 = true;
#pragma unroll
    for (int j = 0; j < 64; j++) {
        long long v = p64[j];
        if (v < 0 || v >= (long long)S) { is64 = false; break; }
    }
    int i = blockIdx.x * blockDim.x + threadIdx.x;
    if (i < NIDX) {
        int v = is64 ? (int)p64[i] : p32[i];
        g_idx[i] = v & (S - 1);
    }
}

// ---------------- kernel: weights -> fp16 m16n8k16 A-fragments ----------------
// A (16x16 = co x ci), row-major. Per-thread regs (gr = lane>>2, tc = lane&3):
//   a0={A[gr][2tc],A[gr][2tc+1]}  a1={A[gr+8][2tc],...}
//   a2={A[gr][2tc+8],A[gr][2tc+9]} a3={A[gr+8][2tc+8],...}
// Stored per (tap, lane): 16 uint4 (m-block 0..3 x kb16 0..3), one LDS.128 each.
__global__ void k_prep(const float* __restrict__ w) {
    int i = blockIdx.x * blockDim.x + threadIdx.x;
    if (i == 0) g_ctr = 0;
    if (i < NW) {
        int co  = i / (C * KS * KS);
        int rem = i - co * (C * KS * KS);
        int ci  = rem / (KS * KS);
        int t   = rem - ci * (KS * KS);
        int m    = co >> 4;
        int r16  = co & 15;
        int gr   = r16 & 7;
        int selm = r16 >> 3;          // 0 -> a0/a2, 1 -> a1/a3
        int kb   = ci >> 4;
        int c16  = ci & 15;
        int selk = c16 >> 3;          // 0 -> a0/a1, 1 -> a2/a3
        int tc   = (c16 & 7) >> 1;
        int lo   = c16 & 1;
        int reg  = selm + 2 * selk;
        int lane = gr * 4 + tc;
        int word = (t * 32 + lane) * WLANE_STRIDE + (m * 4 + kb) * 4 + reg;
        __half hv = __float2half_rn(w[i]);
        ((unsigned short*)g_wf)[word * 2 + lo] = __half_as_ushort(hv);
    }
}

// ---------------- main kernel helpers ----------------
__device__ __forceinline__ void decode_tile(int tau, int& b, int& oh, int& ow0) {
    b = tau >> 9; int r = tau & 511; oh = r >> 1; ow0 = (r & 1) * PX;
}

// gather one tap: 256 gathered fp16 rows (128B each) into padded smem rows (144B)
__device__ __forceinline__ void gather_tap(int b, int oh, int ow0, int t, unsigned dstb) {
    int kh = t / 3, kw = t - 3 * kh;
    const int* ip = g_idx + (3 * oh + kh) * IW + 3 * ow0 + kw;
    const __half* xb = g_xh + (size_t)b * ((size_t)S * C);
    int tid = threadIdx.x;
#pragma unroll
    for (int r = 0; r < (PX * 8) / NTHREADS; r++) {   // 4 iters
        int e  = tid + r * NTHREADS;
        int p  = e >> 3;
        int c8 = e & 7;
        int sidx = ip[3 * p];
        cp_async16(dstb + (unsigned)(p * 144 + c8 * 16),
                   xb + ((size_t)sidx << 6) + (c8 << 3));
    }
    asm volatile("cp.async.commit_group;");
}

// ---------------- main kernel: persistent, fp16 mma ----------------
__global__ void __launch_bounds__(NTHREADS, 1)
k_mma(const float* __restrict__ bias, float* __restrict__ out) {
    unsigned* sm = (unsigned*)dynsmem;
    __shared__ int s_next;

    const int tid  = threadIdx.x;
    const int wid  = tid >> 5;      // 16 warps: each covers all 64 co x 16 px
    const int lane = tid & 31;
    const int gr   = lane >> 2;
    const int tc   = lane & 3;

    // stage weight fragments (78 KB) once
    {
        const uint4* src = (const uint4*)g_wf;
        uint4* dst = (uint4*)sm;
        for (int i = tid; i < WF_WORDS / 4; i += NTHREADS) dst[i] = src[i];
    }

    // bias per c-row: co = m*16 + gr (+8)
    float bco[4][2];
#pragma unroll
    for (int m = 0; m < 4; m++) {
        bco[m][0] = bias[m * 16 + gr];
        bco[m][1] = bias[m * 16 + gr + 8];
    }

    const unsigned sbase = smem_u32(sm);
    const unsigned sx0b  = sbase + SM_X0 * 4;
    const unsigned sx1b  = sbase + SM_X1 * 4;

    if (tid == 0) s_next = atomicAdd(&g_ctr, 1);
    __syncthreads();   // also covers weight staging
    int tau = s_next;
    int pb = 0;

    if (tau < NTILES) {
        int b, oh, ow0; decode_tile(tau, b, oh, ow0);
        gather_tap(b, oh, ow0, 0, sx0b);
    }

    while (tau < NTILES) {
        if (tid == 0) s_next = atomicAdd(&g_ctr, 1);
        int b, oh, ow0; decode_tile(tau, b, oh, ow0);

        float acc[4][2][4];
#pragma unroll
        for (int m = 0; m < 4; m++)
#pragma unroll
            for (int nb = 0; nb < 2; nb++)
#pragma unroll
                for (int c = 0; c < 4; c++) acc[m][nb][c] = 0.0f;

        __syncthreads();          // publish s_next
        int ntau = s_next;
        int nb_ = 0, noh = 0, now0 = 0;
        if (ntau < NTILES) decode_tile(ntau, nb_, noh, now0);

        for (int t = 0; t < 9; t++) {
            bool pf = true;
            unsigned nxt = (pb ^ 1) ? sx1b : sx0b;
            if (t < 8)              gather_tap(b, oh, ow0, t + 1, nxt);
            else if (ntau < NTILES) gather_tap(nb_, noh, now0, 0, nxt);
            else                    pf = false;
            if (pf) asm volatile("cp.async.wait_group 1;");
            else    asm volatile("cp.async.wait_group 0;");
            __syncthreads();

            // compute tap t from buffer pb
            const unsigned* xw = sm + (pb ? SM_X1 : SM_X0);
            const unsigned* wf = sm + (t * 32 + lane) * WLANE_STRIDE;
            const int n0 = wid * 16;        // this warp's px slice
#pragma unroll
            for (int kb = 0; kb < 4; kb++) {
                uint4 A[4];
#pragma unroll
                for (int m = 0; m < 4; m++)
                    A[m] = *(const uint4*)(wf + (m * 4 + kb) * 4);
                unsigned bfr[2][2];
#pragma unroll
                for (int nb = 0; nb < 2; nb++) {
                    // B frag: b0 = half2 @ ci 2tc (word tc), b1 = @ ci 2tc+8 (word tc+4)
                    const unsigned* xp = xw + (n0 + nb * 8 + gr) * XSTRIDE + kb * 8 + tc;
                    bfr[nb][0] = xp[0];
                    bfr[nb][1] = xp[4];
                }
#pragma unroll
                for (int m = 0; m < 4; m++)
#pragma unroll
                    for (int nb = 0; nb < 2; nb++)
                        mma_f16(acc[m][nb], (const unsigned*)&A[m],
                                bfr[nb][0], bfr[nb][1]);
            }
            __syncthreads();       // before next gather overwrites this buffer
            pb ^= 1;
        }

        // epilogue: c0/c1 -> (co=m*16+gr, px=2tc,2tc+1), c2/c3 -> co+8
        {
            float* obase = out + (size_t)b * C * S + (size_t)oh * W + ow0 + wid * 16;
#pragma unroll
            for (int m = 0; m < 4; m++) {
                int co0 = m * 16 + gr;
#pragma unroll
                for (int nb = 0; nb < 2; nb++) {
                    int px = nb * 8 + 2 * tc;
                    float2 v0 = make_float2(acc[m][nb][0] + bco[m][0],
                                            acc[m][nb][1] + bco[m][0]);
                    *(float2*)(obase + (size_t)co0 * S + px) = v0;
                    float2 v1 = make_float2(acc[m][nb][2] + bco[m][1],
                                            acc[m][nb][3] + bco[m][1]);
                    *(float2*)(obase + (size_t)(co0 + 8) * S + px) = v1;
                }
            }
        }
        tau = ntau;
    }
}

// ---------------- host launch ----------------
extern "C" void kernel_launch(void* const* d_in, const int* in_sizes, int n_in,
                              void* d_out, int out_size) {
    (void)in_sizes; (void)n_in; (void)out_size;
    const float* x    = (const float*)d_in[0];
    const void*  idx  = d_in[1];
    const float* w    = (const float*)d_in[2];
    const float* bias = (const float*)d_in[3];
    float* out = (float*)d_out;

    k_transpose<<<dim3(S / 32, C / 32, B), dim3(32, 8)>>>(x);
    k_idx<<<(NIDX + 1023) / 1024, 1024>>>(idx);
    k_prep<<<(NW + 255) / 256, 256>>>(w);

    cudaFuncSetAttribute(k_mma, cudaFuncAttributeMaxDynamicSharedMemorySize, SMEM_BYTES);
    k_mma<<<148, NTHREADS, SMEM_BYTES>>>(bias, out);
}

// round 16
// speedup vs baseline: 4.2076x; 1.1569x over previous
#include <cuda_runtime.h>
#include <cuda_fp16.h>
#include <cstdint>

// ---------------- problem constants ----------------
constexpr int KS = 3;
constexpr int B  = 4, C = 64, H = 256, W = 512;
constexpr int S  = H * W;                 // 131072
constexpr int IW = KS * W;                // 1536
constexpr int NIDX = KS * H * KS * W;     // 1179648
constexpr int NW   = C * C * KS * KS;     // 36864

constexpr int PX      = 512;              // pixels per tile = one full output row
constexpr int NTILES  = B * H;            // 1024
constexpr int NTHREADS = 512;             // 16 warps, 32 px each

// smem layout (32-bit words)
constexpr int WLANE_STRIDE = 68;              // 64 frag words + 4 pad
constexpr int WF_WORDS   = 9 * 32 * WLANE_STRIDE;   // 19584 words = 78336 B
constexpr int XSTRIDE    = 36;                // 32 data words (64 half) + 4 pad
constexpr int XBUF_WORDS = PX * XSTRIDE;      // 18432 words = 73728 B per buffer
constexpr int SM_X0 = WF_WORDS;
constexpr int SM_X1 = WF_WORDS + XBUF_WORDS;
constexpr int SMEM_BYTES = (WF_WORDS + 2 * XBUF_WORDS) * 4;   // 225792

// ---------------- device scratch ----------------
__device__ __half   g_xh[(size_t)B * S * C];  // x transposed [b][s][c], fp16
__device__ int      g_idx[NIDX];
__device__ unsigned g_wf[WF_WORDS];           // fp16 weights in m16n8k16 A-fragment order
__device__ int      g_ctr;

extern __shared__ char dynsmem[];

// ---------------- ptx helpers ----------------
__device__ __forceinline__ unsigned smem_u32(const void* p) {
    unsigned a;
    asm("{ .reg .u64 t; cvta.to.shared.u64 t, %1; cvt.u32.u64 %0, t; }" : "=r"(a) : "l"(p));
    return a;
}
__device__ __forceinline__ void cp_async16(unsigned dst, const void* src) {
    asm volatile("cp.async.cg.shared.global [%0], [%1], 16;" :: "r"(dst), "l"(src));
}
__device__ __forceinline__ void mma_f16(float c[4], const unsigned a[4],
                                        unsigned b0, unsigned b1) {
    asm volatile(
        "mma.sync.aligned.m16n8k16.row.col.f32.f16.f16.f32 "
        "{%0,%1,%2,%3}, {%4,%5,%6,%7}, {%8,%9}, {%0,%1,%2,%3};"
        : "+f"(c[0]), "+f"(c[1]), "+f"(c[2]), "+f"(c[3])
        : "r"(a[0]), "r"(a[1]), "r"(a[2]), "r"(a[3]), "r"(b0), "r"(b1));
}

// ---------------- kernel: transpose x[b][c][s] -> g_xh[b][s][c] (fp16) ----------
__global__ void k_transpose(const float* __restrict__ x) {
    __shared__ float tile[32][33];
    int b  = blockIdx.z;
    int c0 = blockIdx.y * 32;
    int s0 = blockIdx.x * 32;
    const float* xp = x + ((size_t)(b * C + c0)) * S + s0;
#pragma unroll
    for (int i = 0; i < 32; i += 8)
        tile[threadIdx.y + i][threadIdx.x] = xp[(size_t)(threadIdx.y + i) * S + threadIdx.x];
    __syncthreads();
    __half* op = g_xh + ((size_t)b * S + s0) * C + c0;
    int t = threadIdx.x;
    if (t < 16) {
#pragma unroll
        for (int i = 0; i < 32; i += 8) {
            int row = threadIdx.y + i;
            half2 v = __floats2half2_rn(tile[2 * t][row], tile[2 * t + 1][row]);
            ((half2*)(op + (size_t)row * C))[t] = v;
        }
    }
}

// ---------------- kernel: idx (int32 OR int64, auto-detected) ----------------
__global__ void k_idx(const void* __restrict__ idxraw) {
    const long long* p64 = (const long long*)idxraw;
    const int*       p32 = (const int*)idxraw;
    bool is64 = true;
#pragma unroll
    for (int j = 0; j < 64; j++) {
        long long v = p64[j];
        if (v < 0 || v >= (long long)S) { is64 = false; break; }
    }
    int i = blockIdx.x * blockDim.x + threadIdx.x;
    if (i < NIDX) {
        int v = is64 ? (int)p64[i] : p32[i];
        g_idx[i] = v & (S - 1);
    }
}

// ---------------- kernel: weights -> fp16 m16n8k16 A-fragments ----------------
__global__ void k_prep(const float* __restrict__ w) {
    int i = blockIdx.x * blockDim.x + threadIdx.x;
    if (i == 0) g_ctr = 0;
    if (i < NW) {
        int co  = i / (C * KS * KS);
        int rem = i - co * (C * KS * KS);
        int ci  = rem / (KS * KS);
        int t   = rem - ci * (KS * KS);
        int m    = co >> 4;
        int r16  = co & 15;
        int gr   = r16 & 7;
        int selm = r16 >> 3;
        int kb   = ci >> 4;
        int c16  = ci & 15;
        int selk = c16 >> 3;
        int tc   = (c16 & 7) >> 1;
        int lo   = c16 & 1;
        int reg  = selm + 2 * selk;
        int lane = gr * 4 + tc;
        int word = (t * 32 + lane) * WLANE_STRIDE + (m * 4 + kb) * 4 + reg;
        __half hv = __float2half_rn(w[i]);
        ((unsigned short*)g_wf)[word * 2 + lo] = __half_as_ushort(hv);
    }
}

// ---------------- main kernel helpers ----------------
__device__ __forceinline__ void decode_tile(int tau, int& b, int& oh) {
    b = tau >> 8; oh = tau & 255;
}

// gather one tap: 512 gathered fp16 rows (128B each) into padded smem rows (144B)
__device__ __forceinline__ void gather_tap(int b, int oh, int t, unsigned dstb) {
    int kh = t / 3, kw = t - 3 * kh;
    const int* ip = g_idx + (3 * oh + kh) * IW + kw;
    const __half* xb = g_xh + (size_t)b * ((size_t)S * C);
    int tid = threadIdx.x;
#pragma unroll
    for (int r = 0; r < (PX * 8) / NTHREADS; r++) {   // 8 iters
        int e  = tid + r * NTHREADS;
        int p  = e >> 3;
        int c8 = e & 7;
        int sidx = ip[3 * p];
        cp_async16(dstb + (unsigned)(p * 144 + c8 * 16),
                   xb + ((size_t)sidx << 6) + (c8 << 3));
    }
    asm volatile("cp.async.commit_group;");
}

// ---------------- main kernel: persistent, fp16 mma, 512-px tiles ------------
__global__ void __launch_bounds__(NTHREADS, 1)
k_mma(const float* __restrict__ bias, float* __restrict__ out) {
    unsigned* sm = (unsigned*)dynsmem;
    __shared__ int s_next;

    const int tid  = threadIdx.x;
    const int wid  = tid >> 5;      // 16 warps: each covers 64 co x 32 px
    const int lane = tid & 31;
    const int gr   = lane >> 2;
    const int tc   = lane & 3;

    // stage weight fragments (78 KB) once
    {
        const uint4* src = (const uint4*)g_wf;
        uint4* dst = (uint4*)sm;
        for (int i = tid; i < WF_WORDS / 4; i += NTHREADS) dst[i] = src[i];
    }

    // bias per c-row: co = m*16 + gr (+8)
    float bco[4][2];
#pragma unroll
    for (int m = 0; m < 4; m++) {
        bco[m][0] = bias[m * 16 + gr];
        bco[m][1] = bias[m * 16 + gr + 8];
    }

    const unsigned sbase = smem_u32(sm);
    const unsigned sx0b  = sbase + SM_X0 * 4;
    const unsigned sx1b  = sbase + SM_X1 * 4;

    if (tid == 0) s_next = atomicAdd(&g_ctr, 1);
    __syncthreads();   // also covers weight staging
    int tau = s_next;
    int pb = 0;

    if (tau < NTILES) {
        int b, oh; decode_tile(tau, b, oh);
        gather_tap(b, oh, 0, sx0b);
    }

    while (tau < NTILES) {
        if (tid == 0) s_next = atomicAdd(&g_ctr, 1);
        int b, oh; decode_tile(tau, b, oh);

        float acc[4][4][4];   // [m][nb][c] : 64 floats
#pragma unroll
        for (int m = 0; m < 4; m++)
#pragma unroll
            for (int nb = 0; nb < 4; nb++)
#pragma unroll
                for (int c = 0; c < 4; c++) acc[m][nb][c] = 0.0f;

        __syncthreads();          // publish s_next
        int ntau = s_next;
        int nb_ = 0, noh = 0;
        if (ntau < NTILES) decode_tile(ntau, nb_, noh);

        for (int t = 0; t < 9; t++) {
            bool pf = true;
            unsigned nxt = (pb ^ 1) ? sx1b : sx0b;
            if (t < 8)              gather_tap(b, oh, t + 1, nxt);
            else if (ntau < NTILES) gather_tap(nb_, noh, 0, nxt);
            else                    pf = false;
            if (pf) asm volatile("cp.async.wait_group 1;");
            else    asm volatile("cp.async.wait_group 0;");
            __syncthreads();

            // compute tap t from buffer pb
            const unsigned* xw = sm + (pb ? SM_X1 : SM_X0);
            const unsigned* wf = sm + (t * 32 + lane) * WLANE_STRIDE;
            const int n0 = wid * 32;        // this warp's px slice
#pragma unroll
            for (int kb = 0; kb < 4; kb++) {
                uint4 A[4];
#pragma unroll
                for (int m = 0; m < 4; m++)
                    A[m] = *(const uint4*)(wf + (m * 4 + kb) * 4);
#pragma unroll
                for (int nb = 0; nb < 4; nb++) {
                    const unsigned* xp = xw + (n0 + nb * 8 + gr) * XSTRIDE + kb * 8 + tc;
                    unsigned b0 = xp[0];
                    unsigned b1 = xp[4];
#pragma unroll
                    for (int m = 0; m < 4; m++)
                        mma_f16(acc[m][nb], (const unsigned*)&A[m], b0, b1);
                }
            }
            __syncthreads();       // before next gather overwrites this buffer
            pb ^= 1;
        }

        // epilogue: c0/c1 -> (co=m*16+gr, px=nb*8+2tc), c2/c3 -> co+8
        {
            float* obase = out + (size_t)b * C * S + (size_t)oh * W + wid * 32;
#pragma unroll
            for (int m = 0; m < 4; m++) {
                int co0 = m * 16 + gr;
#pragma unroll
                for (int nb = 0; nb < 4; nb++) {
                    int px = nb * 8 + 2 * tc;
                    float2 v0 = make_float2(acc[m][nb][0] + bco[m][0],
                                            acc[m][nb][1] + bco[m][0]);
                    *(float2*)(obase + (size_t)co0 * S + px) = v0;
                    float2 v1 = make_float2(acc[m][nb][2] + bco[m][1],
                                            acc[m][nb][3] + bco[m][1]);
                    *(float2*)(obase + (size_t)(co0 + 8) * S + px) = v1;
                }
            }
        }
        tau = ntau;
    }
}

// ---------------- host launch ----------------
extern "C" void kernel_launch(void* const* d_in, const int* in_sizes, int n_in,
                              void* d_out, int out_size) {
    (void)in_sizes; (void)n_in; (void)out_size;
    const float* x    = (const float*)d_in[0];
    const void*  idx  = d_in[1];
    const float* w    = (const float*)d_in[2];
    const float* bias = (const float*)d_in[3];
    float* out = (float*)d_out;

    k_transpose<<<dim3(S / 32, C / 32, B), dim3(32, 8)>>>(x);
    k_idx<<<(NIDX + 1023) / 1024, 1024>>>(idx);
    k_prep<<<(NW + 255) / 256, 256>>>(w);

    cudaFuncSetAttribute(k_mma, cudaFuncAttributeMaxDynamicSharedMemorySize, SMEM_BYTES);
    k_mma<<<148, NTHREADS, SMEM_BYTES>>>(bias, out);
}

// round 17
// speedup vs baseline: 5.6094x; 1.3331x over previous
#include <cuda_runtime.h>
#include <cuda_fp16.h>
#include <cstdint>

// ---------------- problem constants ----------------
constexpr int KS = 3;
constexpr int B  = 4, C = 64, H = 256, W = 512;
constexpr int S  = H * W;                 // 131072
constexpr int IW = KS * W;                // 1536
constexpr int NIDX = KS * H * KS * W;     // 1179648
constexpr int NW   = C * C * KS * KS;     // 36864

constexpr int NTHREADS = 512;             // 16 warps per CTA
constexpr int NCTAS    = 148;
constexpr int NWARPS   = NCTAS * 16;      // 2368
constexpr int UNITS    = B * H * 16;      // 16384 (row x 16 slices of 32 px)

// smem layout (32-bit words)
constexpr int WLANE_STRIDE = 68;              // 64 frag words + 4 pad
constexpr int WF_WORDS   = 9 * 32 * WLANE_STRIDE;   // 19584 words = 78336 B
constexpr int XSTRIDE    = 36;                // 32 data words (64 half) + 4 pad
constexpr int XBUF_WORDS = 32 * XSTRIDE;      // 1152 words = 4608 B (one tap, 32 px)
constexpr int WARP_WORDS = 2 * XBUF_WORDS;    // 2304 words = 9216 B per warp
constexpr int SMEM_BYTES = (WF_WORDS + 16 * WARP_WORDS) * 4;   // 225792

// ---------------- device scratch ----------------
__device__ __half   g_xh[(size_t)B * S * C];  // x transposed [b][s][c], fp16
__device__ int      g_idx[NIDX];
__device__ unsigned g_wf[WF_WORDS];           // fp16 weights in m16n8k16 A-fragment order

extern __shared__ char dynsmem[];

// ---------------- ptx helpers ----------------
__device__ __forceinline__ unsigned smem_u32(const void* p) {
    unsigned a;
    asm("{ .reg .u64 t; cvta.to.shared.u64 t, %1; cvt.u32.u64 %0, t; }" : "=r"(a) : "l"(p));
    return a;
}
__device__ __forceinline__ void cp_async16(unsigned dst, const void* src) {
    asm volatile("cp.async.cg.shared.global [%0], [%1], 16;" :: "r"(dst), "l"(src));
}
__device__ __forceinline__ void mma_f16(float c[4], const unsigned a[4],
                                        unsigned b0, unsigned b1) {
    asm volatile(
        "mma.sync.aligned.m16n8k16.row.col.f32.f16.f16.f32 "
        "{%0,%1,%2,%3}, {%4,%5,%6,%7}, {%8,%9}, {%0,%1,%2,%3};"
        : "+f"(c[0]), "+f"(c[1]), "+f"(c[2]), "+f"(c[3])
        : "r"(a[0]), "r"(a[1]), "r"(a[2]), "r"(a[3]), "r"(b0), "r"(b1));
}

// ---------------- kernel: transpose x[b][c][s] -> g_xh[b][s][c] (fp16) ----------
__global__ void k_transpose(const float* __restrict__ x) {
    __shared__ float tile[32][33];
    int b  = blockIdx.z;
    int c0 = blockIdx.y * 32;
    int s0 = blockIdx.x * 32;
    const float* xp = x + ((size_t)(b * C + c0)) * S + s0;
#pragma unroll
    for (int i = 0; i < 32; i += 8)
        tile[threadIdx.y + i][threadIdx.x] = xp[(size_t)(threadIdx.y + i) * S + threadIdx.x];
    __syncthreads();
    __half* op = g_xh + ((size_t)b * S + s0) * C + c0;
    int t = threadIdx.x;
    if (t < 16) {
#pragma unroll
        for (int i = 0; i < 32; i += 8) {
            int row = threadIdx.y + i;
            half2 v = __floats2half2_rn(tile[2 * t][row], tile[2 * t + 1][row]);
            ((half2*)(op + (size_t)row * C))[t] = v;
        }
    }
}

// ---------------- kernel: idx (int32 OR int64, auto-detected) ----------------
__global__ void k_idx(const void* __restrict__ idxraw) {
    const long long* p64 = (const long long*)idxraw;
    const int*       p32 = (const int*)idxraw;
    bool is64 = true;
#pragma unroll
    for (int j = 0; j < 64; j++) {
        long long v = p64[j];
        if (v < 0 || v >= (long long)S) { is64 = false; break; }
    }
    int i = blockIdx.x * blockDim.x + threadIdx.x;
    if (i < NIDX) {
        int v = is64 ? (int)p64[i] : p32[i];
        g_idx[i] = v & (S - 1);
    }
}

// ---------------- kernel: weights -> fp16 m16n8k16 A-fragments ----------------
__global__ void k_prep(const float* __restrict__ w) {
    int i = blockIdx.x * blockDim.x + threadIdx.x;
    if (i < NW) {
        int co  = i / (C * KS * KS);
        int rem = i - co * (C * KS * KS);
        int ci  = rem / (KS * KS);
        int t   = rem - ci * (KS * KS);
        int m    = co >> 4;
        int r16  = co & 15;
        int gr   = r16 & 7;
        int selm = r16 >> 3;
        int kb   = ci >> 4;
        int c16  = ci & 15;
        int selk = c16 >> 3;
        int tc   = (c16 & 7) >> 1;
        int lo   = c16 & 1;
        int reg  = selm + 2 * selk;
        int lane = gr * 4 + tc;
        int word = (t * 32 + lane) * WLANE_STRIDE + (m * 4 + kb) * 4 + reg;
        __half hv = __float2half_rn(w[i]);
        ((unsigned short*)g_wf)[word * 2 + lo] = __half_as_ushort(hv);
    }
}

// ---------------- main kernel: warp-decoupled persistent pipeline ------------
// work unit u: b = u>>12, oh = (u>>4)&255, slice j = u&15 (32 px at 32j)
// each warp owns a private double-buffered 2x4608B X region; NO CTA barriers
// in the mainloop.
__device__ __forceinline__ void gather_unit_tap(int u, int t, unsigned dstb, int lane) {
    int b  = u >> 12;
    int oh = (u >> 4) & 255;
    int j  = u & 15;
    int kh = t / 3, kw = t - 3 * kh;
    const int* ip = g_idx + (3 * oh + kh) * IW + kw + 96 * j;
    const __half* xb = g_xh + (size_t)b * ((size_t)S * C);
#pragma unroll
    for (int r = 0; r < 8; r++) {
        int e  = lane + 32 * r;
        int p  = e >> 3;
        int c8 = e & 7;
        int sidx = ip[3 * p];
        cp_async16(dstb + (unsigned)(p * 144 + c8 * 16),
                   xb + ((size_t)sidx << 6) + (c8 << 3));
    }
    asm volatile("cp.async.commit_group;");
}

__global__ void __launch_bounds__(NTHREADS, 1)
k_mma(const float* __restrict__ bias, float* __restrict__ out) {
    unsigned* sm = (unsigned*)dynsmem;

    const int tid  = threadIdx.x;
    const int wid  = tid >> 5;
    const int lane = tid & 31;
    const int gr   = lane >> 2;
    const int tc   = lane & 3;

    // stage weight fragments (78 KB) once
    {
        const uint4* src = (const uint4*)g_wf;
        uint4* dst = (uint4*)sm;
        for (int i = tid; i < WF_WORDS / 4; i += NTHREADS) dst[i] = src[i];
    }

    float bco[4][2];
#pragma unroll
    for (int m = 0; m < 4; m++) {
        bco[m][0] = bias[m * 16 + gr];
        bco[m][1] = bias[m * 16 + gr + 8];
    }
    __syncthreads();   // weights visible; last CTA-wide barrier

    const unsigned sbase = smem_u32(sm);
    const unsigned mybuf = sbase + (unsigned)(WF_WORDS + wid * WARP_WORDS) * 4u;
    const int wgid = blockIdx.x * 16 + wid;

    int kc = 0;                         // global tap counter (buffer parity)
    int u  = wgid;
    if (u < UNITS) gather_unit_tap(u, 0, mybuf, lane);   // prime buf0

    for (; u < UNITS; u += NWARPS) {
        float acc[4][4][4];
#pragma unroll
        for (int m = 0; m < 4; m++)
#pragma unroll
            for (int nb = 0; nb < 4; nb++)
#pragma unroll
                for (int c = 0; c < 4; c++) acc[m][nb][c] = 0.0f;

        const int b  = u >> 12;
        const int oh = (u >> 4) & 255;
        const int j  = u & 15;

        for (int t = 0; t < 9; t++) {
            // issue next gather into the other buffer (WAR safe: that buffer was
            // fully read in iteration t-1, ordered by program order + syncwarp)
            __syncwarp();
            bool pf = true;
            unsigned nxt = mybuf + (unsigned)((kc + 1) & 1) * 4608u;
            if (t < 8)                    gather_unit_tap(u, t + 1, nxt, lane);
            else if (u + NWARPS < UNITS)  gather_unit_tap(u + NWARPS, 0, nxt, lane);
            else                          pf = false;
            if (pf) asm volatile("cp.async.wait_group 1;");
            else    asm volatile("cp.async.wait_group 0;");
            __syncwarp();               // all lanes' groups retired -> slice visible

            const unsigned* xw = (const unsigned*)(uintptr_t)0;  // (unused-gen guard)
            (void)xw;
            const unsigned* xb = (const unsigned*)dynsmem +
                                 (WF_WORDS + wid * WARP_WORDS) + ((kc & 1) ? XBUF_WORDS : 0);
            const unsigned* wf = (const unsigned*)dynsmem + (t * 32 + lane) * WLANE_STRIDE;
#pragma unroll
            for (int kb = 0; kb < 4; kb++) {
                uint4 A[4];
#pragma unroll
                for (int m = 0; m < 4; m++)
                    A[m] = *(const uint4*)(wf + (m * 4 + kb) * 4);
#pragma unroll
                for (int nb = 0; nb < 4; nb++) {
                    const unsigned* xp = xb + (nb * 8 + gr) * XSTRIDE + kb * 8 + tc;
                    unsigned b0 = xp[0];
                    unsigned b1 = xp[4];
#pragma unroll
                    for (int m = 0; m < 4; m++)
                        mma_f16(acc[m][nb], (const unsigned*)&A[m], b0, b1);
                }
            }
            kc++;
        }

        // epilogue: warp-private store of 64co x 32px
        {
            float* obase = out + (size_t)b * C * S + (size_t)oh * W + 32 * j;
#pragma unroll
            for (int m = 0; m < 4; m++) {
                int co0 = m * 16 + gr;
#pragma unroll
                for (int nb = 0; nb < 4; nb++) {
                    int px = nb * 8 + 2 * tc;
                    float2 v0 = make_float2(acc[m][nb][0] + bco[m][0],
                                            acc[m][nb][1] + bco[m][0]);
                    *(float2*)(obase + (size_t)co0 * S + px) = v0;
                    float2 v1 = make_float2(acc[m][nb][2] + bco[m][1],
                                            acc[m][nb][3] + bco[m][1]);
                    *(float2*)(obase + (size_t)(co0 + 8) * S + px) = v1;
                }
            }
        }
    }
}

// ---------------- host launch ----------------
extern "C" void kernel_launch(void* const* d_in, const int* in_sizes, int n_in,
                              void* d_out, int out_size) {
    (void)in_sizes; (void)n_in; (void)out_size;
    const float* x    = (const float*)d_in[0];
    const void*  idx  = d_in[1];
    const float* w    = (const float*)d_in[2];
    const float* bias = (const float*)d_in[3];
    float* out = (float*)d_out;

    k_transpose<<<dim3(S / 32, C / 32, B), dim3(32, 8)>>>(x);
    k_idx<<<(NIDX + 1023) / 1024, 1024>>>(idx);
    k_prep<<<(NW + 255) / 256, 256>>>(w);

    cudaFuncSetAttribute(k_mma, cudaFuncAttributeMaxDynamicSharedMemorySize, SMEM_BYTES);
    k_mma<<<NCTAS, NTHREADS, SMEM_BYTES>>>(bias, out);
}